// round 13
// baseline (speedup 1.0000x reference)
#include <cuda_runtime.h>
#include <cstdint>

#define Bn 32
#define Tn 1024
#define In 512
#define Hn 1024
#define Gn 4096   // 4*Hn
#define NB 128    // persistent blocks (1 block/SM)
#define NT 512    // phase-2 threads

// ---------------- device scratch (static: no allocation allowed) ----------------
__device__ float g_xpre[(size_t)Tn * Bn * Gn];  // [T][B][4H], biases folded in
__device__ float g_h[2 * Bn * Hn];              // ping-pong hidden state
__device__ float g_c[Bn * Hn];                  // cell state (block-exclusive ranges)
__device__ unsigned g_count;                    // grid barrier arrivals (monotonic)
__device__ volatile unsigned g_gen;             // grid barrier generation

typedef unsigned long long ull;

__device__ __forceinline__ ull fma2(ull a, ull b, ull c) {
    ull d; asm("fma.rn.f32x2 %0, %1, %2, %3;" : "=l"(d) : "l"(a), "l"(b), "l"(c)); return d;
}
__device__ __forceinline__ ull pack2(float lo, float hi) {
    ull r; asm("mov.b64 %0, {%1, %2};" : "=l"(r) : "f"(lo), "f"(hi)); return r;
}
__device__ __forceinline__ void unpack2(ull v, float& a, float& b) {
    asm("mov.b64 {%0, %1}, %2;" : "=f"(a), "=f"(b) : "l"(v));
}

// ---------------- phase 1 (+init): Xpre = inputs @ W_ih^T + b_ih + b_hh ----------------
// (validated) M = T*B = 32768, N = 4096, K = 512. 128x128 tiles, f32x2.
__global__ __launch_bounds__(256) void prep_gemm(
    const float* __restrict__ X,    // [B][T][I]
    const float* __restrict__ Wih,  // [4H][I]
    const float* __restrict__ bih,
    const float* __restrict__ bhh)
{
    __shared__ float As[2][16][132];
    __shared__ float Bs[2][16][132];

    int tid = threadIdx.x;
    int bx = blockIdx.x, by = blockIdx.y;

    // ---- fused init of state/barrier ----
    {
        int fb = by * 32 + bx;
        int idx = fb * 256 + tid;
        if (idx < 2 * Bn * Hn) g_h[idx] = 0.0f;
        if (idx < Bn * Hn)     g_c[idx] = 0.0f;
        if (idx == 0) { g_count = 0; g_gen = 0; }
    }

    int sr = tid & 127;
    int sk = (tid >> 7) * 8;
    int mg = by * 128 + sr;
    const float* arow = X + ((size_t)(mg & 31) * Tn + (mg >> 5)) * In;
    const float* brow = Wih + (size_t)(bx * 128 + sr) * In;

    int tm = tid >> 4;
    int tn = tid & 15;

    ull acc[8][4];
#pragma unroll
    for (int i = 0; i < 8; i++)
#pragma unroll
        for (int p = 0; p < 4; p++) acc[i][p] = 0ULL;

    float4 pa0, pa1, pb0, pb1;
    pa0 = *(const float4*)(arow + sk);
    pa1 = *(const float4*)(arow + sk + 4);
    pb0 = *(const float4*)(brow + sk);
    pb1 = *(const float4*)(brow + sk + 4);
#pragma unroll
    for (int j = 0; j < 4; j++) {
        As[0][sk + j][sr]     = ((const float*)&pa0)[j];
        As[0][sk + 4 + j][sr] = ((const float*)&pa1)[j];
        Bs[0][sk + j][sr]     = ((const float*)&pb0)[j];
        Bs[0][sk + 4 + j][sr] = ((const float*)&pb1)[j];
    }
    __syncthreads();

    for (int kt = 0; kt < 32; kt++) {
        if (kt < 31) {
            int k0 = (kt + 1) * 16;
            pa0 = *(const float4*)(arow + k0 + sk);
            pa1 = *(const float4*)(arow + k0 + sk + 4);
            pb0 = *(const float4*)(brow + k0 + sk);
            pb1 = *(const float4*)(brow + k0 + sk + 4);
        }
        int buf = kt & 1;
#pragma unroll
        for (int k = 0; k < 16; k++) {
            float a[8];
            *(float4*)&a[0] = *(const float4*)&As[buf][k][tm * 8];
            *(float4*)&a[4] = *(const float4*)&As[buf][k][tm * 8 + 4];
            float4 b0 = *(const float4*)&Bs[buf][k][tn * 8];
            float4 b1 = *(const float4*)&Bs[buf][k][tn * 8 + 4];
            ull bv[4];
            bv[0] = *(const ull*)&b0.x; bv[1] = *(const ull*)&b0.z;
            bv[2] = *(const ull*)&b1.x; bv[3] = *(const ull*)&b1.z;
#pragma unroll
            for (int i = 0; i < 8; i++) {
                ull ap = pack2(a[i], a[i]);
#pragma unroll
                for (int p = 0; p < 4; p++)
                    acc[i][p] = fma2(ap, bv[p], acc[i][p]);
            }
        }
        if (kt < 31) {
            int nb = (kt + 1) & 1;
#pragma unroll
            for (int j = 0; j < 4; j++) {
                As[nb][sk + j][sr]     = ((const float*)&pa0)[j];
                As[nb][sk + 4 + j][sr] = ((const float*)&pa1)[j];
                Bs[nb][sk + j][sr]     = ((const float*)&pb0)[j];
                Bs[nb][sk + 4 + j][sr] = ((const float*)&pb1)[j];
            }
        }
        __syncthreads();
    }

    int ng = bx * 128 + tn * 8;
    float bias[8];
#pragma unroll
    for (int j = 0; j < 8; j++) bias[j] = bih[ng + j] + bhh[ng + j];
#pragma unroll
    for (int i = 0; i < 8; i++) {
        int m = by * 128 + tm * 8 + i;
        float* dst = g_xpre + (size_t)m * Gn + ng;
#pragma unroll
        for (int p = 0; p < 4; p++) {
            float lo, hi; unpack2(acc[i][p], lo, hi);
            *(float2*)(dst + 2 * p) = make_float2(lo + bias[2 * p], hi + bias[2 * p + 1]);
        }
    }
}

// ---------------- phase 2: persistent LSTM, 512 threads ----------------
// Block owns 32 gate rows (4 gates x 8 units) x 32 batches, K=1024.
// W_hh resident in smem (transposed Ws[k][36], row = gate*8 + unit).
// h window: 256-k double-buffered, plain (no dup), Hw[256][36] -> 4 tiles, 4 syncs/step.
// 8-way k-split (kq = tid>>6, 32 k per tile per thread).
// Micro-tile: 4 rows x 4 batches; pairs built via pack2 (ALU pipe), 8 fma2/kl.
#define WS_STRIDE 36
#define WS_FLOATS (Hn * WS_STRIDE)            // 36864
#define HW_STRIDE 36
#define HW_BUF (256 * HW_STRIDE)              // 9216 floats
#define HW_FLOATS (2 * HW_BUF)                // 18432 (P overlay needs 8448)
#define GB_FLOATS (32 * 33)                   // 1056
#define SMEM2_FLOATS (WS_FLOATS + HW_FLOATS + GB_FLOATS)
#define SMEM2_BYTES (SMEM2_FLOATS * 4)        // 225,408 B <= 227 KB

__global__ __launch_bounds__(NT, 1) void lstm_persist(
    const float* __restrict__ Whh,  // [4H][H]
    float* __restrict__ out)
{
    extern __shared__ float sm[];
    float* Ws   = sm;                          // [1024][36]
    float* Hw   = sm + WS_FLOATS;              // [2][256][36] / P overlay [8][32][33]
    float* gbuf = sm + WS_FLOATS + HW_FLOATS;  // [32][33]
    float* P    = Hw;

    int tid = threadIdx.x;
    int bid = blockIdx.x;

    // ---- stage W_hh slice (once): Ws[k*36 + r], r = gate*8 + unit ----
    {
        int r   = tid >> 4;            // 0..31
        int kq4 = (tid & 15) * 4;
        int grow = (r >> 3) * Hn + bid * 8 + (r & 7);
        const float* wr = Whh + (size_t)grow * Hn;
#pragma unroll 4
        for (int m = 0; m < 16; m++) {
            int k = m * 64 + kq4;
            float4 v = *(const float4*)(wr + k);
            Ws[(k + 0) * WS_STRIDE + r] = v.x;
            Ws[(k + 1) * WS_STRIDE + r] = v.y;
            Ws[(k + 2) * WS_STRIDE + r] = v.z;
            Ws[(k + 3) * WS_STRIDE + r] = v.w;
        }
    }

    // compute mapping
    int kq  = tid >> 6;          // 0..7 k-group (32 k per 256-k tile)
    int t6  = tid & 63;
    int rg  = t6 >> 3;           // 0..7 -> rows 4rg..4rg+3
    int bgr = t6 & 7;            // 0..7 -> batches 4bgr..4bgr+3
    // staging mapping: lane = batch (conflict-free STS), 2x 8-k chunks per tile
    int sb  = tid & 31;          // batch
    int sc  = tid >> 5;          // 0..15 -> k-chunks sc*8 and 128+sc*8 within tile
    // elementwise mapping (tid < 256)
    int eb = tid >> 3;           // batch 0..31
    int ej = tid & 7;            // unit 0..7
    int hidx = bid * 8 + ej;
    int ci = eb * Hn + hidx;

    __syncthreads();

    for (int t = 0; t < Tn; t++) {
        const float* hin = g_h + (t & 1) * (Bn * Hn);
        float* hout      = g_h + ((t + 1) & 1) * (Bn * Hn);
        const float* hrow = hin + sb * Hn;

        float xpi, xpf, xpg, xpo;
        if (tid < 256) {
            const float* xp = g_xpre + ((size_t)t * Bn + eb) * Gn;
            xpi = __ldg(xp + hidx);
            xpf = __ldg(xp + Hn + hidx);
            xpg = __ldg(xp + 2 * Hn + hidx);
            xpo = __ldg(xp + 3 * Hn + hidx);
        }

        // ---- stage tile 0 into buf 0 (32B contiguous per lane, STS conflict-free) ----
        {
            float4 a0 = __ldcg((const float4*)(hrow + sc * 8));
            float4 a1 = __ldcg((const float4*)(hrow + sc * 8 + 4));
            float4 b0 = __ldcg((const float4*)(hrow + 128 + sc * 8));
            float4 b1 = __ldcg((const float4*)(hrow + 128 + sc * 8 + 4));
            float* d0 = Hw + (sc * 8) * HW_STRIDE + sb;
            float* d1 = Hw + (128 + sc * 8) * HW_STRIDE + sb;
            const float* p;
            p = (const float*)&a0;
#pragma unroll
            for (int j = 0; j < 4; j++) d0[j * HW_STRIDE] = p[j];
            p = (const float*)&a1;
#pragma unroll
            for (int j = 0; j < 4; j++) d0[(4 + j) * HW_STRIDE] = p[j];
            p = (const float*)&b0;
#pragma unroll
            for (int j = 0; j < 4; j++) d1[j * HW_STRIDE] = p[j];
            p = (const float*)&b1;
#pragma unroll
            for (int j = 0; j < 4; j++) d1[(4 + j) * HW_STRIDE] = p[j];
        }
        __syncthreads();

        ull acc[2][4];
#pragma unroll
        for (int p = 0; p < 2; p++)
#pragma unroll
            for (int b = 0; b < 4; b++) acc[p][b] = 0ULL;

        for (int tile = 0; tile < 4; tile++) {
            float4 a0, a1, b0, b1;
            if (tile < 3) {
                const float* nx = hrow + (tile + 1) * 256;
                a0 = __ldcg((const float4*)(nx + sc * 8));
                a1 = __ldcg((const float4*)(nx + sc * 8 + 4));
                b0 = __ldcg((const float4*)(nx + 128 + sc * 8));
                b1 = __ldcg((const float4*)(nx + 128 + sc * 8 + 4));
            }
            int buf = tile & 1;
            const float* wk = Ws + (size_t)(tile * 256 + kq * 32) * WS_STRIDE + 4 * rg;
            const float* hk = Hw + buf * HW_BUF + (kq * 32) * HW_STRIDE + 4 * bgr;
#pragma unroll 8
            for (int kl = 0; kl < 32; kl++) {
                ulonglong2 w = *(const ulonglong2*)(wk + kl * WS_STRIDE);
                float4 hv = *(const float4*)(hk + kl * HW_STRIDE);
                ull hx = pack2(hv.x, hv.x);
                ull hy = pack2(hv.y, hv.y);
                ull hz = pack2(hv.z, hv.z);
                ull hw2 = pack2(hv.w, hv.w);
                acc[0][0] = fma2(w.x, hx, acc[0][0]);
                acc[1][0] = fma2(w.y, hx, acc[1][0]);
                acc[0][1] = fma2(w.x, hy, acc[0][1]);
                acc[1][1] = fma2(w.y, hy, acc[1][1]);
                acc[0][2] = fma2(w.x, hz, acc[0][2]);
                acc[1][2] = fma2(w.y, hz, acc[1][2]);
                acc[0][3] = fma2(w.x, hw2, acc[0][3]);
                acc[1][3] = fma2(w.y, hw2, acc[1][3]);
            }
            if (tile < 3) {
                float* d0 = Hw + (buf ^ 1) * HW_BUF + (sc * 8) * HW_STRIDE + sb;
                float* d1 = Hw + (buf ^ 1) * HW_BUF + (128 + sc * 8) * HW_STRIDE + sb;
                const float* p;
                p = (const float*)&a0;
#pragma unroll
                for (int j = 0; j < 4; j++) d0[j * HW_STRIDE] = p[j];
                p = (const float*)&a1;
#pragma unroll
                for (int j = 0; j < 4; j++) d0[(4 + j) * HW_STRIDE] = p[j];
                p = (const float*)&b0;
#pragma unroll
                for (int j = 0; j < 4; j++) d1[j * HW_STRIDE] = p[j];
                p = (const float*)&b1;
#pragma unroll
                for (int j = 0; j < 4; j++) d1[(4 + j) * HW_STRIDE] = p[j];
            }
            __syncthreads();
        }

        // ---- write per-k-group partials into P (overlay of Hw; reads done) ----
#pragma unroll
        for (int p = 0; p < 2; p++)
#pragma unroll
            for (int b = 0; b < 4; b++) {
                float lo, hi; unpack2(acc[p][b], lo, hi);
                int col = 4 * bgr + b;
                P[kq * 1056 + (4 * rg + 2 * p)     * 33 + col] = lo;
                P[kq * 1056 + (4 * rg + 2 * p + 1) * 33 + col] = hi;
            }
        __syncthreads();

        // ---- reduce 8 k-groups: 1024 outputs, 2 per thread ----
#pragma unroll
        for (int rep = 0; rep < 2; rep++) {
            int gid = tid + rep * NT;
            int row = gid >> 5, b = gid & 31;
            float s = 0.0f;
#pragma unroll
            for (int q = 0; q < 8; q++) s += P[q * 1056 + row * 33 + b];
            gbuf[row * 33 + b] = s;
        }
        __syncthreads();

        // ---- LSTM elementwise (256 cells) ----
        if (tid < 256) {
            float pi  = gbuf[(0  + ej) * 33 + eb] + xpi;
            float pf_ = gbuf[(8  + ej) * 33 + eb] + xpf;
            float pg  = gbuf[(16 + ej) * 33 + eb] + xpg;
            float po  = gbuf[(24 + ej) * 33 + eb] + xpo;
            float ig = 1.0f / (1.0f + __expf(-pi));
            float fg = 1.0f / (1.0f + __expf(-pf_));
            float gg = tanhf(pg);
            float og = 1.0f / (1.0f + __expf(-po));
            float c = fg * g_c[ci] + ig * gg;
            float h = og * tanhf(c);
            g_c[ci]  = c;
            hout[ci] = h;
            out[((size_t)eb * Tn + t) * Hn + hidx] = h;
            if (t == Tn - 1) {
                out[(size_t)Bn * Tn * Hn + ci]           = h;  // h_T
                out[(size_t)Bn * Tn * Hn + Bn * Hn + ci] = c;  // c_T
            }
        }

        // ---- grid barrier (validated pattern) ----
        if (t < Tn - 1) {
            __threadfence();
            __syncthreads();
            if (tid == 0) {
                unsigned target = (unsigned)NB * (unsigned)(t + 1);
                if (atomicAdd(&g_count, 1u) == target - 1u) {
                    __threadfence();
                    g_gen = (unsigned)(t + 1);
                } else {
                    while (g_gen < (unsigned)(t + 1)) { }
                    __threadfence();
                }
            }
            __syncthreads();
        }
    }
}

// ---------------- launch ----------------
extern "C" void kernel_launch(void* const* d_in, const int* in_sizes, int n_in,
                              void* d_out, int out_size)
{
    const float* X   = (const float*)d_in[0];
    const float* Wih = (const float*)d_in[1];
    const float* Whh = (const float*)d_in[2];
    const float* bih = (const float*)d_in[3];
    const float* bhh = (const float*)d_in[4];
    float* out = (float*)d_out;

    cudaFuncSetAttribute(lstm_persist, cudaFuncAttributeMaxDynamicSharedMemorySize, SMEM2_BYTES);

    prep_gemm<<<dim3(Gn / 128, (Tn * Bn) / 128), 256>>>(X, Wih, bih, bhh);
    lstm_persist<<<NB, NT, SMEM2_BYTES>>>(Whh, out);
}

// round 14
// speedup vs baseline: 1.5737x; 1.5737x over previous
#include <cuda_runtime.h>
#include <cstdint>

#define Bn 32
#define Tn 1024
#define In 512
#define Hn 1024
#define Gn 4096   // 4*Hn
#define NB 128    // persistent blocks (1 block/SM)
#define NT 512    // phase-2 threads

// ---------------- device scratch (static: no allocation allowed) ----------------
__device__ float g_xpre[(size_t)Tn * Bn * Gn];  // [T][B][4H], biases folded in
__device__ float g_h[2 * Bn * Hn];              // ping-pong hidden state, TRANSPOSED: hT[j][b]
__device__ float g_c[Bn * Hn];                  // cell state (block-exclusive ranges)
__device__ unsigned g_count;                    // grid barrier arrivals (monotonic)
__device__ volatile unsigned g_gen;             // grid barrier generation

typedef unsigned long long ull;

__device__ __forceinline__ ull fma2(ull a, ull b, ull c) {
    ull d; asm("fma.rn.f32x2 %0, %1, %2, %3;" : "=l"(d) : "l"(a), "l"(b), "l"(c)); return d;
}
__device__ __forceinline__ ull pack2(float lo, float hi) {
    ull r; asm("mov.b64 %0, {%1, %2};" : "=l"(r) : "f"(lo), "f"(hi)); return r;
}
__device__ __forceinline__ void unpack2(ull v, float& a, float& b) {
    asm("mov.b64 {%0, %1}, %2;" : "=f"(a), "=f"(b) : "l"(v));
}

// ---------------- phase 1 (+init): Xpre = inputs @ W_ih^T + b_ih + b_hh ----------------
// (validated) M = T*B = 32768, N = 4096, K = 512. 128x128 tiles, f32x2.
__global__ __launch_bounds__(256) void prep_gemm(
    const float* __restrict__ X,    // [B][T][I]
    const float* __restrict__ Wih,  // [4H][I]
    const float* __restrict__ bih,
    const float* __restrict__ bhh)
{
    __shared__ float As[2][16][132];
    __shared__ float Bs[2][16][132];

    int tid = threadIdx.x;
    int bx = blockIdx.x, by = blockIdx.y;

    // ---- fused init of state/barrier ----
    {
        int fb = by * 32 + bx;
        int idx = fb * 256 + tid;
        if (idx < 2 * Bn * Hn) g_h[idx] = 0.0f;
        if (idx < Bn * Hn)     g_c[idx] = 0.0f;
        if (idx == 0) { g_count = 0; g_gen = 0; }
    }

    int sr = tid & 127;
    int sk = (tid >> 7) * 8;
    int mg = by * 128 + sr;
    const float* arow = X + ((size_t)(mg & 31) * Tn + (mg >> 5)) * In;
    const float* brow = Wih + (size_t)(bx * 128 + sr) * In;

    int tm = tid >> 4;
    int tn = tid & 15;

    ull acc[8][4];
#pragma unroll
    for (int i = 0; i < 8; i++)
#pragma unroll
        for (int p = 0; p < 4; p++) acc[i][p] = 0ULL;

    float4 pa0, pa1, pb0, pb1;
    pa0 = *(const float4*)(arow + sk);
    pa1 = *(const float4*)(arow + sk + 4);
    pb0 = *(const float4*)(brow + sk);
    pb1 = *(const float4*)(brow + sk + 4);
#pragma unroll
    for (int j = 0; j < 4; j++) {
        As[0][sk + j][sr]     = ((const float*)&pa0)[j];
        As[0][sk + 4 + j][sr] = ((const float*)&pa1)[j];
        Bs[0][sk + j][sr]     = ((const float*)&pb0)[j];
        Bs[0][sk + 4 + j][sr] = ((const float*)&pb1)[j];
    }
    __syncthreads();

    for (int kt = 0; kt < 32; kt++) {
        if (kt < 31) {
            int k0 = (kt + 1) * 16;
            pa0 = *(const float4*)(arow + k0 + sk);
            pa1 = *(const float4*)(arow + k0 + sk + 4);
            pb0 = *(const float4*)(brow + k0 + sk);
            pb1 = *(const float4*)(brow + k0 + sk + 4);
        }
        int buf = kt & 1;
#pragma unroll
        for (int k = 0; k < 16; k++) {
            float a[8];
            *(float4*)&a[0] = *(const float4*)&As[buf][k][tm * 8];
            *(float4*)&a[4] = *(const float4*)&As[buf][k][tm * 8 + 4];
            float4 b0 = *(const float4*)&Bs[buf][k][tn * 8];
            float4 b1 = *(const float4*)&Bs[buf][k][tn * 8 + 4];
            ull bv[4];
            bv[0] = *(const ull*)&b0.x; bv[1] = *(const ull*)&b0.z;
            bv[2] = *(const ull*)&b1.x; bv[3] = *(const ull*)&b1.z;
#pragma unroll
            for (int i = 0; i < 8; i++) {
                ull ap = pack2(a[i], a[i]);
#pragma unroll
                for (int p = 0; p < 4; p++)
                    acc[i][p] = fma2(ap, bv[p], acc[i][p]);
            }
        }
        if (kt < 31) {
            int nb = (kt + 1) & 1;
#pragma unroll
            for (int j = 0; j < 4; j++) {
                As[nb][sk + j][sr]     = ((const float*)&pa0)[j];
                As[nb][sk + 4 + j][sr] = ((const float*)&pa1)[j];
                Bs[nb][sk + j][sr]     = ((const float*)&pb0)[j];
                Bs[nb][sk + 4 + j][sr] = ((const float*)&pb1)[j];
            }
        }
        __syncthreads();
    }

    int ng = bx * 128 + tn * 8;
    float bias[8];
#pragma unroll
    for (int j = 0; j < 8; j++) bias[j] = bih[ng + j] + bhh[ng + j];
#pragma unroll
    for (int i = 0; i < 8; i++) {
        int m = by * 128 + tm * 8 + i;
        float* dst = g_xpre + (size_t)m * Gn + ng;
#pragma unroll
        for (int p = 0; p < 4; p++) {
            float lo, hi; unpack2(acc[i][p], lo, hi);
            *(float2*)(dst + 2 * p) = make_float2(lo + bias[2 * p], hi + bias[2 * p + 1]);
        }
    }
}

// ---------------- phase 2: persistent LSTM, 512 threads ----------------
// Block owns 32 gate rows (4 gates x 8 units) x 32 batches, K=1024.
// W_hh resident in smem (transposed Ws[k][36], row = gate*8 + unit).
// h lives TRANSPOSED in global: hT[j][b] ([1024][32]) -> staging LDG is contiguous
// (nL=4 per warp instr) and STS.128 drops straight into k-major Hw[k][36].
// h window: 256-k double-buffered -> 4 tiles, 4 syncs/step.
// 8-way k-split (kq = tid>>6, 32 k per tile per thread).
// Micro-tile: 4 rows x 4 batches; pairs built via pack2 (ALU pipe), 8 fma2/kl.
#define WS_STRIDE 36
#define WS_FLOATS (Hn * WS_STRIDE)            // 36864
#define HW_STRIDE 36
#define HW_BUF (256 * HW_STRIDE)              // 9216 floats
#define HW_FLOATS (2 * HW_BUF)                // 18432 (P overlay needs 8448)
#define GB_FLOATS (32 * 33)                   // 1056
#define SMEM2_FLOATS (WS_FLOATS + HW_FLOATS + GB_FLOATS)
#define SMEM2_BYTES (SMEM2_FLOATS * 4)        // 225,408 B <= 227 KB

__global__ __launch_bounds__(NT, 1) void lstm_persist(
    const float* __restrict__ Whh,  // [4H][H]
    float* __restrict__ out)
{
    extern __shared__ float sm[];
    float* Ws   = sm;                          // [1024][36]
    float* Hw   = sm + WS_FLOATS;              // [2][256][36] / P overlay [8][32][33]
    float* gbuf = sm + WS_FLOATS + HW_FLOATS;  // [32][33]
    float* P    = Hw;

    int tid = threadIdx.x;
    int bid = blockIdx.x;

    // ---- stage W_hh slice (once): Ws[k*36 + r], r = gate*8 + unit ----
    {
        int r   = tid >> 4;            // 0..31
        int kq4 = (tid & 15) * 4;
        int grow = (r >> 3) * Hn + bid * 8 + (r & 7);
        const float* wr = Whh + (size_t)grow * Hn;
#pragma unroll 4
        for (int m = 0; m < 16; m++) {
            int k = m * 64 + kq4;
            float4 v = *(const float4*)(wr + k);
            Ws[(k + 0) * WS_STRIDE + r] = v.x;
            Ws[(k + 1) * WS_STRIDE + r] = v.y;
            Ws[(k + 2) * WS_STRIDE + r] = v.z;
            Ws[(k + 3) * WS_STRIDE + r] = v.w;
        }
    }

    // compute mapping
    int kq  = tid >> 6;          // 0..7 k-group (32 k per 256-k tile)
    int t6  = tid & 63;
    int rg  = t6 >> 3;           // 0..7 -> rows 4rg..4rg+3
    int bgr = t6 & 7;            // 0..7 -> batches 4bgr..4bgr+3
    // staging mapping: thread -> batch-group sg (4 batches), k-rows skr + 64*i
    int sg  = tid & 7;           // 0..7
    int skr = tid >> 3;          // 0..63
    // elementwise mapping (tid < 256)
    int eb = tid >> 3;           // batch 0..31
    int ej = tid & 7;            // unit 0..7
    int hidx = bid * 8 + ej;
    int ci = eb * Hn + hidx;

    __syncthreads();

    for (int t = 0; t < Tn; t++) {
        const float* hinT = g_h + (t & 1) * (Bn * Hn);        // hT[j][b]
        float* houtT      = g_h + ((t + 1) & 1) * (Bn * Hn);

        float xpi, xpf, xpg, xpo;
        if (tid < 256) {
            const float* xp = g_xpre + ((size_t)t * Bn + eb) * Gn;
            xpi = __ldg(xp + hidx);
            xpf = __ldg(xp + Hn + hidx);
            xpg = __ldg(xp + 2 * Hn + hidx);
            xpo = __ldg(xp + 3 * Hn + hidx);
        }

        // ---- stage tile 0 into buf 0 (contiguous LDG nL=4, direct STS.128) ----
        {
#pragma unroll
            for (int i = 0; i < 4; i++) {
                int kr = skr + 64 * i;
                float4 v = __ldcg((const float4*)(hinT + kr * Bn + 4 * sg));
                *(float4*)(Hw + kr * HW_STRIDE + 4 * sg) = v;
            }
        }
        __syncthreads();

        ull acc[2][4];
#pragma unroll
        for (int p = 0; p < 2; p++)
#pragma unroll
            for (int b = 0; b < 4; b++) acc[p][b] = 0ULL;

        for (int tile = 0; tile < 4; tile++) {
            float4 pv[4];
            if (tile < 3) {
#pragma unroll
                for (int i = 0; i < 4; i++) {
                    int kr = (tile + 1) * 256 + skr + 64 * i;
                    pv[i] = __ldcg((const float4*)(hinT + kr * Bn + 4 * sg));
                }
            }
            int buf = tile & 1;
            const float* wk = Ws + (size_t)(tile * 256 + kq * 32) * WS_STRIDE + 4 * rg;
            const float* hk = Hw + buf * HW_BUF + (kq * 32) * HW_STRIDE + 4 * bgr;
#pragma unroll 8
            for (int kl = 0; kl < 32; kl++) {
                ulonglong2 w = *(const ulonglong2*)(wk + kl * HW_STRIDE);
                float4 hv = *(const float4*)(hk + kl * HW_STRIDE);
                ull hx = pack2(hv.x, hv.x);
                ull hy = pack2(hv.y, hv.y);
                ull hz = pack2(hv.z, hv.z);
                ull hw2 = pack2(hv.w, hv.w);
                acc[0][0] = fma2(w.x, hx, acc[0][0]);
                acc[1][0] = fma2(w.y, hx, acc[1][0]);
                acc[0][1] = fma2(w.x, hy, acc[0][1]);
                acc[1][1] = fma2(w.y, hy, acc[1][1]);
                acc[0][2] = fma2(w.x, hz, acc[0][2]);
                acc[1][2] = fma2(w.y, hz, acc[1][2]);
                acc[0][3] = fma2(w.x, hw2, acc[0][3]);
                acc[1][3] = fma2(w.y, hw2, acc[1][3]);
            }
            if (tile < 3) {
                float* dbuf = Hw + (buf ^ 1) * HW_BUF;
#pragma unroll
                for (int i = 0; i < 4; i++) {
                    int kr = skr + 64 * i;
                    *(float4*)(dbuf + kr * HW_STRIDE + 4 * sg) = pv[i];
                }
            }
            __syncthreads();
        }

        // ---- write per-k-group partials into P (overlay of Hw; reads done) ----
#pragma unroll
        for (int p = 0; p < 2; p++)
#pragma unroll
            for (int b = 0; b < 4; b++) {
                float lo, hi; unpack2(acc[p][b], lo, hi);
                int col = 4 * bgr + b;
                P[kq * 1056 + (4 * rg + 2 * p)     * 33 + col] = lo;
                P[kq * 1056 + (4 * rg + 2 * p + 1) * 33 + col] = hi;
            }
        __syncthreads();

        // ---- reduce 8 k-groups: 1024 outputs, 2 per thread ----
#pragma unroll
        for (int rep = 0; rep < 2; rep++) {
            int gid = tid + rep * NT;
            int row = gid >> 5, b = gid & 31;
            float s = 0.0f;
#pragma unroll
            for (int q = 0; q < 8; q++) s += P[q * 1056 + row * 33 + b];
            gbuf[row * 33 + b] = s;
        }
        __syncthreads();

        // ---- LSTM elementwise (256 cells) ----
        if (tid < 256) {
            float pi  = gbuf[(0  + ej) * 33 + eb] + xpi;
            float pf_ = gbuf[(8  + ej) * 33 + eb] + xpf;
            float pg  = gbuf[(16 + ej) * 33 + eb] + xpg;
            float po  = gbuf[(24 + ej) * 33 + eb] + xpo;
            float ig = 1.0f / (1.0f + __expf(-pi));
            float fg = 1.0f / (1.0f + __expf(-pf_));
            float gg = tanhf(pg);
            float og = 1.0f / (1.0f + __expf(-po));
            float c = fg * g_c[ci] + ig * gg;
            float h = og * tanhf(c);
            g_c[ci] = c;
            houtT[hidx * Bn + eb] = h;     // transposed hidden state
            out[((size_t)eb * Tn + t) * Hn + hidx] = h;
            if (t == Tn - 1) {
                out[(size_t)Bn * Tn * Hn + ci]           = h;  // h_T
                out[(size_t)Bn * Tn * Hn + Bn * Hn + ci] = c;  // c_T
            }
        }

        // ---- grid barrier (validated pattern) ----
        if (t < Tn - 1) {
            __threadfence();
            __syncthreads();
            if (tid == 0) {
                unsigned target = (unsigned)NB * (unsigned)(t + 1);
                if (atomicAdd(&g_count, 1u) == target - 1u) {
                    __threadfence();
                    g_gen = (unsigned)(t + 1);
                } else {
                    while (g_gen < (unsigned)(t + 1)) { }
                    __threadfence();
                }
            }
            __syncthreads();
        }
    }
}

// ---------------- launch ----------------
extern "C" void kernel_launch(void* const* d_in, const int* in_sizes, int n_in,
                              void* d_out, int out_size)
{
    const float* X   = (const float*)d_in[0];
    const float* Wih = (const float*)d_in[1];
    const float* Whh = (const float*)d_in[2];
    const float* bih = (const float*)d_in[3];
    const float* bhh = (const float*)d_in[4];
    float* out = (float*)d_out;

    cudaFuncSetAttribute(lstm_persist, cudaFuncAttributeMaxDynamicSharedMemorySize, SMEM2_BYTES);

    prep_gemm<<<dim3(Gn / 128, (Tn * Bn) / 128), 256>>>(X, Wih, bih, bhh);
    lstm_persist<<<NB, NT, SMEM2_BYTES>>>(Whh, out);
}